// round 9
// baseline (speedup 1.0000x reference)
#include <cuda_runtime.h>
#include <cuda_bf16.h>
#include <stdint.h>
#include <math.h>

#define NS 50000
#define NA 50000
#define NEDGE 1600000

// Scratch (device globals; no allocation allowed)
__device__ __align__(16) float g_Apre[NA * 32];
__device__ __align__(16) float g_Bpre[NS * 32];
__device__ __align__(16) float g_Cpre[NS * 32];
__device__ __align__(16) float g_Dpre[NS * 32];
__device__ __align__(16) float g_sum_u[NS * 64];
__device__ __align__(16) float g_sum_h[NS * 64];

__device__ __forceinline__ float leaky(float x) { return fmaxf(x, 0.01f * x); }
__device__ __forceinline__ float tanh_fast(float x) {
    float r; asm("tanh.approx.f32 %0, %1;" : "=f"(r) : "f"(x)); return r;
}
__device__ __forceinline__ uint32_t smem_u32(const void* p) {
    uint32_t a;
    asm("{ .reg .u64 t; cvta.to.shared.u64 t, %1; cvt.u32.u64 %0, t; }"
        : "=r"(a) : "l"(p));
    return a;
}
__device__ __forceinline__ uint32_t pack_bf16x2(__nv_bfloat16 a, __nv_bfloat16 b) {
    uint16_t ua = *reinterpret_cast<uint16_t*>(&a);
    uint16_t ub = *reinterpret_cast<uint16_t*>(&b);
    return (uint32_t)ua | ((uint32_t)ub << 16);
}
__device__ __forceinline__ uint32_t cvt_bf16x2(float lo_elem, float hi_elem) {
    uint32_t r;
    asm("cvt.rn.bf16x2.f32 %0, %1, %2;" : "=r"(r) : "f"(hi_elem), "f"(lo_elem));
    return r;
}
__device__ __forceinline__ void ldsm_x4(uint32_t addr, uint32_t& a0, uint32_t& a1,
                                        uint32_t& a2, uint32_t& a3) {
    asm volatile("ldmatrix.sync.aligned.m8n8.x4.shared.b16 {%0,%1,%2,%3}, [%4];"
                 : "=r"(a0), "=r"(a1), "=r"(a2), "=r"(a3) : "r"(addr));
}
__device__ __forceinline__ void mma_bf16(float& c0, float& c1, float& c2, float& c3,
                                         uint32_t a0, uint32_t a1, uint32_t a2, uint32_t a3,
                                         uint32_t b0, uint32_t b1) {
    asm volatile(
        "mma.sync.aligned.m16n8k16.row.col.f32.bf16.bf16.f32 "
        "{%0,%1,%2,%3}, {%4,%5,%6,%7}, {%8,%9}, {%0,%1,%2,%3};"
        : "+f"(c0), "+f"(c1), "+f"(c2), "+f"(c3)
        : "r"(a0), "r"(a1), "r"(a2), "r"(a3), "r"(b0), "r"(b1));
}
__device__ __forceinline__ void red_v4(float* p, float a, float b, float c, float d) {
    asm volatile("red.global.add.v4.f32 [%0], {%1, %2, %3, %4};"
                 :: "l"(p), "f"(a), "f"(b), "f"(c), "f"(d) : "memory");
}

// Dummy kernels: steer ncu's captured launch (#4 overall) onto edge_mma_kernel.
__global__ void noop_kernel() {}

// ---------------------------------------------------------------------------
// Fused node-side precompute (unchanged)
// ---------------------------------------------------------------------------
__global__ void __launch_bounds__(256) pre_kernel(
    const float* __restrict__ pos_s,
    const float* __restrict__ pos_a,
    const float* __restrict__ u,
    const float* __restrict__ h,
    const float* __restrict__ a2s_W1, const float* __restrict__ a2s_b1,
    const float* __restrict__ s2s_W1, const float* __restrict__ s2s_b1)
{
    int lane = threadIdx.x & 31;
    int task = (blockIdx.x * blockDim.x + threadIdx.x) >> 5;

    if (task < NS) {
        int node = task;
        float p0 = __ldg(pos_s + 2 * node);
        float p1 = __ldg(pos_s + 2 * node + 1);
        g_Bpre[node * 32 + lane] =
            p0 * __ldg(a2s_W1 + 2 * 32 + lane) + p1 * __ldg(a2s_W1 + 3 * 32 + lane);
        g_Dpre[node * 32 + lane] =
            p0 * __ldg(s2s_W1 + 2 * 32 + lane) + p1 * __ldg(s2s_W1 + 3 * 32 + lane);
        g_sum_u[node * 64 + lane]      = 0.f;
        g_sum_u[node * 64 + 32 + lane] = 0.f;
        g_sum_h[node * 64 + lane]      = 0.f;
        g_sum_h[node * 64 + 32 + lane] = 0.f;
    } else if (task < NS + NA) {
        int node = task - NS;
        const float* W1 = a2s_W1;
        float p0 = __ldg(pos_a + 2 * node);
        float p1 = __ldg(pos_a + 2 * node + 1);
        float acc = __ldg(a2s_b1 + lane)
                  + p0 * __ldg(W1 + 0 * 32 + lane)
                  + p1 * __ldg(W1 + 1 * 32 + lane);
        const float4* u4 = reinterpret_cast<const float4*>(u) + node * 4;
#pragma unroll
        for (int q = 0; q < 4; ++q) {
            float4 v = __ldg(u4 + q);
            acc = fmaf(v.x, __ldg(W1 + (5 + 4 * q + 0) * 32 + lane), acc);
            acc = fmaf(v.y, __ldg(W1 + (5 + 4 * q + 1) * 32 + lane), acc);
            acc = fmaf(v.z, __ldg(W1 + (5 + 4 * q + 2) * 32 + lane), acc);
            acc = fmaf(v.w, __ldg(W1 + (5 + 4 * q + 3) * 32 + lane), acc);
        }
        g_Apre[node * 32 + lane] = acc;
    } else if (task < NS + NA + NS) {
        int node = task - NS - NA;
        const float* W1 = s2s_W1;
        float p0 = __ldg(pos_s + 2 * node);
        float p1 = __ldg(pos_s + 2 * node + 1);
        float acc = __ldg(s2s_b1 + lane)
                  + p0 * __ldg(W1 + 0 * 32 + lane)
                  + p1 * __ldg(W1 + 1 * 32 + lane);
        const float4* h4 = reinterpret_cast<const float4*>(h) + node * 16;
#pragma unroll
        for (int q = 0; q < 16; ++q) {
            float4 v = __ldg(h4 + q);
            acc = fmaf(v.x, __ldg(W1 + (5 + 4 * q + 0) * 32 + lane), acc);
            acc = fmaf(v.y, __ldg(W1 + (5 + 4 * q + 1) * 32 + lane), acc);
            acc = fmaf(v.z, __ldg(W1 + (5 + 4 * q + 2) * 32 + lane), acc);
            acc = fmaf(v.w, __ldg(W1 + (5 + 4 * q + 3) * 32 + lane), acc);
        }
        g_Cpre[node * 32 + lane] = acc;
    }
}

// ---------------------------------------------------------------------------
// Edge kernel, mma.sync bf16 3-term split (fragment math verified R5-R8).
// R9: epilogue regroups lane pairs via shfl.xor so each edge's 64-float
// scatter issues as 16 lanes x red.v4 instead of 32 lanes x red.v2
// (halves REDG lane count at the LSU).
// Blocks [0,EB) = a2s, [EB,2EB) = s2s.  NEDGE % 256 == 0.
// ---------------------------------------------------------------------------
#define ROWB 192   // A-tile row stride in bytes (hi at +0..63, lo at +64..127)

__global__ void __launch_bounds__(128, 5) edge_mma_kernel(
    int eb,
    const int* __restrict__ src0, const int* __restrict__ dst0,
    const float* __restrict__ dis0,
    const float* __restrict__ W10, const float* __restrict__ W20,
    const float* __restrict__ b20,
    const int* __restrict__ src1, const int* __restrict__ dst1,
    const float* __restrict__ dis1,
    const float* __restrict__ W11, const float* __restrict__ W21,
    const float* __restrict__ b21)
{
    __shared__ __align__(16) char sA[4][32 * ROWB];          // 24576 B
    __shared__ __align__(16) uint32_t sBF[2][8][32][4];      // 8192 B
    __shared__ __align__(16) float sb2[64];                  // 256 B

    int tid  = threadIdx.x;
    int wid  = tid >> 5;
    int lane = tid & 31;

    bool second = (blockIdx.x >= (unsigned)eb);
    int blk = second ? ((int)blockIdx.x - eb) : (int)blockIdx.x;

    const int*   src = second ? src1 : src0;
    const int*   dst = second ? dst1 : dst0;
    const float* dis = second ? dis1 : dis0;
    const float* W1  = second ? W11  : W10;
    const float* W2  = second ? W21  : W20;
    const float* b2  = second ? b21  : b20;
    const float* __restrict__ Asrc = second ? g_Cpre : g_Apre;
    const float* __restrict__ Bdst = second ? g_Dpre : g_Bpre;
    float* __restrict__ sumbuf     = second ? g_sum_h : g_sum_u;

    // ---- bias copy + B-fragment table (once per CTA) ----
    if (tid < 64) sb2[tid] = __ldg(b2 + tid);
#pragma unroll
    for (int f = tid; f < 2048; f += 128) {
        int w      = f & 3;
        int lane_i = (f >> 2) & 31;
        int g      = (f >> 7) & 7;
        int half   = f >> 10;
        int nt_l   = g >> 1;
        int kt     = g & 1;
        int n  = (half * 4 + nt_l) * 8 + (lane_i >> 2);
        int k0 = kt * 16 + 2 * (lane_i & 3) + (w & 1) * 8;
        float w0 = __ldg(W2 + (k0 + 0) * 64 + n);
        float w1 = __ldg(W2 + (k0 + 1) * 64 + n);
        __nv_bfloat16 h0 = __float2bfloat16(w0);
        __nv_bfloat16 h1 = __float2bfloat16(w1);
        uint32_t val;
        if ((w >> 1) == 0) {
            val = pack_bf16x2(h0, h1);
        } else {
            val = pack_bf16x2(__float2bfloat16(w0 - __bfloat162float(h0)),
                              __float2bfloat16(w1 - __bfloat162float(h1)));
        }
        sBF[half][g][lane_i][w] = val;
    }
    __syncthreads();

    char* warp_tile = sA[wid];
    uint32_t tile_base = smem_u32(warp_tile);

    int eslot = lane >> 3;
    int echunk = lane & 7;
    float4 w1d4 = __ldg(reinterpret_cast<const float4*>(W1 + 4 * 32) + echunk);

    uint32_t lrow   = ((lane >> 3) & 1) * 8 + (lane & 7);
    uint32_t lchunk = (lane >> 4) * 16;

    int q      = lane & 3;
    bool evenq = ((q & 1) == 0);
    int colq   = 4 * (q >> 1);           // 4-col group base within 8-col nt group

    int gwarp = blk * 4 + wid;

#pragma unroll 1
    for (int tile = 0; tile < 2; ++tile) {
        int ebase = gwarp * 64 + tile * 32;
        int s    = __ldg(src + ebase + lane);
        int d    = __ldg(dst + ebase + lane);
        float dv = __ldg(dis + ebase + lane);

        // ---- stage hid tile: 8 iterations x 4 edges ----
#pragma unroll 2
        for (int t = 0; t < 8; ++t) {
            int e = t * 4 + eslot;
            int ss   = __shfl_sync(0xffffffffu, s, e);
            int dd   = __shfl_sync(0xffffffffu, d, e);
            float dw = __shfl_sync(0xffffffffu, dv, e);
            float4 av = __ldg(reinterpret_cast<const float4*>(Asrc + ss * 32) + echunk);
            float4 bv = __ldg(reinterpret_cast<const float4*>(Bdst + dd * 32) + echunk);
            float h0 = leaky(av.x + bv.x + dw * w1d4.x);
            float h1 = leaky(av.y + bv.y + dw * w1d4.y);
            float h2 = leaky(av.z + bv.z + dw * w1d4.z);
            float h3 = leaky(av.w + bv.w + dw * w1d4.w);
            uint32_t hi01 = cvt_bf16x2(h0, h1);
            uint32_t hi23 = cvt_bf16x2(h2, h3);
            float l0 = h0 - __uint_as_float(hi01 << 16);
            float l1 = h1 - __uint_as_float(hi01 & 0xffff0000u);
            float l2 = h2 - __uint_as_float(hi23 << 16);
            float l3 = h3 - __uint_as_float(hi23 & 0xffff0000u);
            uint32_t lo01 = cvt_bf16x2(l0, l1);
            uint32_t lo23 = cvt_bf16x2(l2, l3);
            char* rowp = warp_tile + e * ROWB + echunk * 8;
            *reinterpret_cast<uint2*>(rowp)      = make_uint2(hi01, hi23);
            *reinterpret_cast<uint2*>(rowp + 64) = make_uint2(lo01, lo23);
        }
        __syncwarp();

#pragma unroll
        for (int half = 0; half < 2; ++half) {
            // ---- load B fragments for this half: 8x LDS.128 ----
            uint32_t Bh[4][2][2], Bl[4][2][2];
#pragma unroll
            for (int g = 0; g < 8; ++g) {
                uint4 v = *reinterpret_cast<const uint4*>(&sBF[half][g][lane][0]);
                int nt = g >> 1, kt = g & 1;
                Bh[nt][kt][0] = v.x;
                Bh[nt][kt][1] = v.y;
                Bl[nt][kt][0] = v.z;
                Bl[nt][kt][1] = v.w;
            }

#pragma unroll
            for (int mt = 0; mt < 2; ++mt) {
                uint32_t rbase = tile_base + (mt * 16 + lrow) * ROWB + lchunk;
                uint32_t ah[2][4], al[2][4];
                ldsm_x4(rbase + 0,  ah[0][0], ah[0][1], ah[0][2], ah[0][3]);
                ldsm_x4(rbase + 32, ah[1][0], ah[1][1], ah[1][2], ah[1][3]);
                ldsm_x4(rbase + 64, al[0][0], al[0][1], al[0][2], al[0][3]);
                ldsm_x4(rbase + 96, al[1][0], al[1][1], al[1][2], al[1][3]);

                float C[4][4];
#pragma unroll
                for (int nt = 0; nt < 4; ++nt) {
                    float2 bb = *reinterpret_cast<const float2*>(
                        &sb2[(half * 4 + nt) * 8 + 2 * (lane & 3)]);
                    C[nt][0] = bb.x;
                    C[nt][1] = bb.y;
                    C[nt][2] = bb.x;
                    C[nt][3] = bb.y;
                }

#pragma unroll
                for (int nt = 0; nt < 4; ++nt) {
#pragma unroll
                    for (int kt = 0; kt < 2; ++kt) {
                        mma_bf16(C[nt][0], C[nt][1], C[nt][2], C[nt][3],
                                 ah[kt][0], ah[kt][1], ah[kt][2], ah[kt][3],
                                 Bh[nt][kt][0], Bh[nt][kt][1]);
                        mma_bf16(C[nt][0], C[nt][1], C[nt][2], C[nt][3],
                                 ah[kt][0], ah[kt][1], ah[kt][2], ah[kt][3],
                                 Bl[nt][kt][0], Bl[nt][kt][1]);
                        mma_bf16(C[nt][0], C[nt][1], C[nt][2], C[nt][3],
                                 al[kt][0], al[kt][1], al[kt][2], al[kt][3],
                                 Bh[nt][kt][0], Bh[nt][kt][1]);
                    }
                }

                // ---- epilogue for (half, mt): tanh + pair-swap + red.v4 ----
                // Lane pair (q even, q odd) regroups 2x(2-col, 2 rows) into
                // 1x(4-col, 1 row) each: even lane -> row r (dd0),
                // odd lane -> row r+8 (dd1). Cols: (half*4+nt)*8 + colq + 0..3
                int dd0 = __shfl_sync(0xffffffffu, d, mt * 16 + (lane >> 2));
                int dd1 = __shfl_sync(0xffffffffu, d, mt * 16 + 8 + (lane >> 2));
                int ddme = evenq ? dd0 : dd1;
                float* rowp = sumbuf + (size_t)ddme * 64 + half * 32 + colq;
#pragma unroll
                for (int nt = 0; nt < 4; ++nt) {
                    float t0 = tanh_fast(C[nt][0]);
                    float t1 = tanh_fast(C[nt][1]);
                    float t2 = tanh_fast(C[nt][2]);
                    float t3 = tanh_fast(C[nt][3]);
                    float x0 = __shfl_xor_sync(0xffffffffu, t0, 1);
                    float x1 = __shfl_xor_sync(0xffffffffu, t1, 1);
                    float x2 = __shfl_xor_sync(0xffffffffu, t2, 1);
                    float x3 = __shfl_xor_sync(0xffffffffu, t3, 1);
                    float v0 = evenq ? t0 : x2;
                    float v1 = evenq ? t1 : x3;
                    float v2 = evenq ? x0 : t2;
                    float v3 = evenq ? x1 : t3;
                    red_v4(rowp + nt * 8, v0, v1, v2, v3);
                }
            }
        }
        __syncwarp();
    }
}

// ---------------------------------------------------------------------------
// Node update (unchanged)
// ---------------------------------------------------------------------------
__global__ void __launch_bounds__(256) upd_kernel(
    const float* __restrict__ pos_s,
    const float* __restrict__ h,
    const float* __restrict__ W1,
    const float* __restrict__ b1,
    const float* __restrict__ W2,
    const float* __restrict__ b2,
    float* __restrict__ out)
{
    int lane = threadIdx.x & 31;
    int node = (blockIdx.x * blockDim.x + threadIdx.x) >> 5;
    if (node >= NS) return;
    float p0 = __ldg(pos_s + 2 * node);
    float p1 = __ldg(pos_s + 2 * node + 1);
    float acc = __ldg(b1 + lane)
              + p0 * __ldg(W1 + 0 * 32 + lane)
              + p1 * __ldg(W1 + 1 * 32 + lane);

    const float4* h4  = reinterpret_cast<const float4*>(h) + node * 16;
    const float4* su4 = reinterpret_cast<const float4*>(g_sum_u) + node * 16;
    const float4* sh4 = reinterpret_cast<const float4*>(g_sum_h) + node * 16;
#pragma unroll
    for (int q = 0; q < 16; ++q) {
        float4 v = __ldg(h4 + q);
        acc = fmaf(v.x, __ldg(W1 + (2 + 4 * q + 0) * 32 + lane), acc);
        acc = fmaf(v.y, __ldg(W1 + (2 + 4 * q + 1) * 32 + lane), acc);
        acc = fmaf(v.z, __ldg(W1 + (2 + 4 * q + 2) * 32 + lane), acc);
        acc = fmaf(v.w, __ldg(W1 + (2 + 4 * q + 3) * 32 + lane), acc);
    }
#pragma unroll
    for (int q = 0; q < 16; ++q) {
        float4 v = su4[q];
        acc = fmaf(v.x, __ldg(W1 + (66 + 4 * q + 0) * 32 + lane), acc);
        acc = fmaf(v.y, __ldg(W1 + (66 + 4 * q + 1) * 32 + lane), acc);
        acc = fmaf(v.z, __ldg(W1 + (66 + 4 * q + 2) * 32 + lane), acc);
        acc = fmaf(v.w, __ldg(W1 + (66 + 4 * q + 3) * 32 + lane), acc);
    }
#pragma unroll
    for (int q = 0; q < 16; ++q) {
        float4 v = sh4[q];
        acc = fmaf(v.x, __ldg(W1 + (130 + 4 * q + 0) * 32 + lane), acc);
        acc = fmaf(v.y, __ldg(W1 + (130 + 4 * q + 1) * 32 + lane), acc);
        acc = fmaf(v.z, __ldg(W1 + (130 + 4 * q + 2) * 32 + lane), acc);
        acc = fmaf(v.w, __ldg(W1 + (130 + 4 * q + 3) * 32 + lane), acc);
    }
    acc = leaky(acc);

    float m0 = __ldg(b2 + 2 * lane);
    float m1 = __ldg(b2 + 2 * lane + 1);
#pragma unroll
    for (int k = 0; k < 32; ++k) {
        float hv = __shfl_sync(0xffffffffu, acc, k);
        float2 wv = __ldg(reinterpret_cast<const float2*>(W2 + k * 64) + lane);
        m0 = fmaf(hv, wv.x, m0);
        m1 = fmaf(hv, wv.y, m1);
    }
    float2 o;
    o.x = tanhf(m0);
    o.y = tanhf(m1);
    reinterpret_cast<float2*>(out)[node * 32 + lane] = o;
}

// ---------------------------------------------------------------------------
extern "C" void kernel_launch(void* const* d_in, const int* in_sizes, int n_in,
                              void* d_out, int out_size)
{
    const float* h        = (const float*)d_in[0];
    const float* u        = (const float*)d_in[1];
    const float* pos_s    = (const float*)d_in[2];
    const float* pos_a    = (const float*)d_in[3];
    const float* dis_a2s  = (const float*)d_in[4];
    const float* dis_s2s  = (const float*)d_in[5];
    const int*   a2s_src  = (const int*)d_in[6];
    const int*   a2s_dst  = (const int*)d_in[7];
    const int*   s2s_src  = (const int*)d_in[8];
    const int*   s2s_dst  = (const int*)d_in[9];
    const float* a2s_W1   = (const float*)d_in[10];
    const float* a2s_b1   = (const float*)d_in[11];
    const float* a2s_W2   = (const float*)d_in[12];
    const float* a2s_b2   = (const float*)d_in[13];
    const float* s2s_W1   = (const float*)d_in[14];
    const float* s2s_b1   = (const float*)d_in[15];
    const float* s2s_W2   = (const float*)d_in[16];
    const float* s2s_b2   = (const float*)d_in[17];
    const float* upd_W1   = (const float*)d_in[18];
    const float* upd_b1   = (const float*)d_in[19];
    const float* upd_W2   = (const float*)d_in[20];
    const float* upd_b2   = (const float*)d_in[21];
    float* out = (float*)d_out;

    const int WPB = 8;

    // Launch-order padding: edge_mma_kernel lands at overall launch #4
    // (ncu -s 5 -c 1 captures it).
    noop_kernel<<<1, 32>>>();
    noop_kernel<<<1, 32>>>();

    // Fused node-side precompute
    int pre_tasks = NS + NA + NS;
    pre_kernel<<<(pre_tasks + WPB - 1) / WPB, 256>>>(
        pos_s, pos_a, u, h, a2s_W1, a2s_b1, s2s_W1, s2s_b1);

    // Edge passes on tensor cores (mma.sync): 256 edges per CTA
    int eb = NEDGE / 256;                 // 6250 per pass
    edge_mma_kernel<<<2 * eb, 128>>>(
        eb,
        a2s_src, a2s_dst, dis_a2s, a2s_W1, a2s_W2, a2s_b2,
        s2s_src, s2s_dst, dis_s2s, s2s_W1, s2s_W2, s2s_b2);

    // Node update
    upd_kernel<<<(NS + WPB - 1) / WPB, 256>>>(pos_s, h, upd_W1, upd_b1, upd_W2, upd_b2, out);
}

// round 10
// speedup vs baseline: 1.7214x; 1.7214x over previous
#include <cuda_runtime.h>
#include <cuda_bf16.h>
#include <stdint.h>
#include <math.h>

#define NS 50000
#define NA 50000
#define NEDGE 1600000

// Scratch (device globals; no allocation allowed)
__device__ __align__(16) float g_Apre[NA * 32];
__device__ __align__(16) float g_Bpre[NS * 32];
__device__ __align__(16) float g_Cpre[NS * 32];
__device__ __align__(16) float g_Dpre[NS * 32];
__device__ __align__(16) float g_sum_u[NS * 64];
__device__ __align__(16) float g_sum_h[NS * 64];

__device__ __forceinline__ float leaky(float x) { return fmaxf(x, 0.01f * x); }
__device__ __forceinline__ float tanh_fast(float x) {
    float r; asm("tanh.approx.f32 %0, %1;" : "=f"(r) : "f"(x)); return r;
}
__device__ __forceinline__ uint32_t smem_u32(const void* p) {
    uint32_t a;
    asm("{ .reg .u64 t; cvta.to.shared.u64 t, %1; cvt.u32.u64 %0, t; }"
        : "=r"(a) : "l"(p));
    return a;
}
__device__ __forceinline__ uint32_t pack_bf16x2(__nv_bfloat16 a, __nv_bfloat16 b) {
    uint16_t ua = *reinterpret_cast<uint16_t*>(&a);
    uint16_t ub = *reinterpret_cast<uint16_t*>(&b);
    return (uint32_t)ua | ((uint32_t)ub << 16);
}
__device__ __forceinline__ uint32_t cvt_bf16x2(float lo_elem, float hi_elem) {
    uint32_t r;
    asm("cvt.rn.bf16x2.f32 %0, %1, %2;" : "=r"(r) : "f"(hi_elem), "f"(lo_elem));
    return r;
}
__device__ __forceinline__ void ldsm_x4(uint32_t addr, uint32_t& a0, uint32_t& a1,
                                        uint32_t& a2, uint32_t& a3) {
    asm volatile("ldmatrix.sync.aligned.m8n8.x4.shared.b16 {%0,%1,%2,%3}, [%4];"
                 : "=r"(a0), "=r"(a1), "=r"(a2), "=r"(a3) : "r"(addr));
}
__device__ __forceinline__ void mma_bf16(float& c0, float& c1, float& c2, float& c3,
                                         uint32_t a0, uint32_t a1, uint32_t a2, uint32_t a3,
                                         uint32_t b0, uint32_t b1) {
    asm volatile(
        "mma.sync.aligned.m16n8k16.row.col.f32.bf16.bf16.f32 "
        "{%0,%1,%2,%3}, {%4,%5,%6,%7}, {%8,%9}, {%0,%1,%2,%3};"
        : "+f"(c0), "+f"(c1), "+f"(c2), "+f"(c3)
        : "r"(a0), "r"(a1), "r"(a2), "r"(a3), "r"(b0), "r"(b1));
}
__device__ __forceinline__ void red_v2(float* p, float a, float b) {
    asm volatile("red.global.add.v2.f32 [%0], {%1, %2};"
                 :: "l"(p), "f"(a), "f"(b) : "memory");
}

// Dummy kernels: steer ncu's captured launch (#4 overall) onto edge_mma_kernel.
__global__ void noop_kernel() {}

// ---------------------------------------------------------------------------
// Fused node-side precompute (unchanged)
// ---------------------------------------------------------------------------
__global__ void __launch_bounds__(256) pre_kernel(
    const float* __restrict__ pos_s,
    const float* __restrict__ pos_a,
    const float* __restrict__ u,
    const float* __restrict__ h,
    const float* __restrict__ a2s_W1, const float* __restrict__ a2s_b1,
    const float* __restrict__ s2s_W1, const float* __restrict__ s2s_b1)
{
    int lane = threadIdx.x & 31;
    int task = (blockIdx.x * blockDim.x + threadIdx.x) >> 5;

    if (task < NS) {
        int node = task;
        float p0 = __ldg(pos_s + 2 * node);
        float p1 = __ldg(pos_s + 2 * node + 1);
        g_Bpre[node * 32 + lane] =
            p0 * __ldg(a2s_W1 + 2 * 32 + lane) + p1 * __ldg(a2s_W1 + 3 * 32 + lane);
        g_Dpre[node * 32 + lane] =
            p0 * __ldg(s2s_W1 + 2 * 32 + lane) + p1 * __ldg(s2s_W1 + 3 * 32 + lane);
        g_sum_u[node * 64 + lane]      = 0.f;
        g_sum_u[node * 64 + 32 + lane] = 0.f;
        g_sum_h[node * 64 + lane]      = 0.f;
        g_sum_h[node * 64 + 32 + lane] = 0.f;
    } else if (task < NS + NA) {
        int node = task - NS;
        const float* W1 = a2s_W1;
        float p0 = __ldg(pos_a + 2 * node);
        float p1 = __ldg(pos_a + 2 * node + 1);
        float acc = __ldg(a2s_b1 + lane)
                  + p0 * __ldg(W1 + 0 * 32 + lane)
                  + p1 * __ldg(W1 + 1 * 32 + lane);
        const float4* u4 = reinterpret_cast<const float4*>(u) + node * 4;
#pragma unroll
        for (int q = 0; q < 4; ++q) {
            float4 v = __ldg(u4 + q);
            acc = fmaf(v.x, __ldg(W1 + (5 + 4 * q + 0) * 32 + lane), acc);
            acc = fmaf(v.y, __ldg(W1 + (5 + 4 * q + 1) * 32 + lane), acc);
            acc = fmaf(v.z, __ldg(W1 + (5 + 4 * q + 2) * 32 + lane), acc);
            acc = fmaf(v.w, __ldg(W1 + (5 + 4 * q + 3) * 32 + lane), acc);
        }
        g_Apre[node * 32 + lane] = acc;
    } else if (task < NS + NA + NS) {
        int node = task - NS - NA;
        const float* W1 = s2s_W1;
        float p0 = __ldg(pos_s + 2 * node);
        float p1 = __ldg(pos_s + 2 * node + 1);
        float acc = __ldg(s2s_b1 + lane)
                  + p0 * __ldg(W1 + 0 * 32 + lane)
                  + p1 * __ldg(W1 + 1 * 32 + lane);
        const float4* h4 = reinterpret_cast<const float4*>(h) + node * 16;
#pragma unroll
        for (int q = 0; q < 16; ++q) {
            float4 v = __ldg(h4 + q);
            acc = fmaf(v.x, __ldg(W1 + (5 + 4 * q + 0) * 32 + lane), acc);
            acc = fmaf(v.y, __ldg(W1 + (5 + 4 * q + 1) * 32 + lane), acc);
            acc = fmaf(v.z, __ldg(W1 + (5 + 4 * q + 2) * 32 + lane), acc);
            acc = fmaf(v.w, __ldg(W1 + (5 + 4 * q + 3) * 32 + lane), acc);
        }
        g_Cpre[node * 32 + lane] = acc;
    }
}

// ---------------------------------------------------------------------------
// Edge kernel, mma.sync bf16 3-term split (fragment math verified R5-R9).
// R10: epilogue transposes C through a per-warp smem D-tile (stride 288B,
// conflict-free both directions) so each edge's 64-float scatter issues as
// ONE 32-lane row-contiguous red.v2 (2 cache lines) instead of 8 scattered
// lines -> 4x fewer atomic L1tex wavefronts.
// Blocks [0,EB) = a2s, [EB,2EB) = s2s.  NEDGE % 256 == 0.
// ---------------------------------------------------------------------------
#define AROWB 192    // A-tile row stride (staging layout, unchanged)
#define DSTR  288    // D-tile row stride in bytes (72 words == 8 mod 32 banks)
#define WBUF  9216   // 32*288; A-tile (6144B) aliases the front of this

__global__ void __launch_bounds__(128, 4) edge_mma_kernel(
    int eb,
    const int* __restrict__ src0, const int* __restrict__ dst0,
    const float* __restrict__ dis0,
    const float* __restrict__ W10, const float* __restrict__ W20,
    const float* __restrict__ b20,
    const int* __restrict__ src1, const int* __restrict__ dst1,
    const float* __restrict__ dis1,
    const float* __restrict__ W11, const float* __restrict__ W21,
    const float* __restrict__ b21)
{
    __shared__ __align__(16) char sAD[4][WBUF];          // 36864 B
    __shared__ __align__(16) uint32_t sBF[2][8][32][4];  // 8192 B
    __shared__ __align__(16) float sb2[64];              // 256 B

    int tid  = threadIdx.x;
    int wid  = tid >> 5;
    int lane = tid & 31;

    bool second = (blockIdx.x >= (unsigned)eb);
    int blk = second ? ((int)blockIdx.x - eb) : (int)blockIdx.x;

    const int*   src = second ? src1 : src0;
    const int*   dst = second ? dst1 : dst0;
    const float* dis = second ? dis1 : dis0;
    const float* W1  = second ? W11  : W10;
    const float* W2  = second ? W21  : W20;
    const float* b2  = second ? b21  : b20;
    const float* __restrict__ Asrc = second ? g_Cpre : g_Apre;
    const float* __restrict__ Bdst = second ? g_Dpre : g_Bpre;
    float* __restrict__ sumbuf     = second ? g_sum_h : g_sum_u;

    // ---- bias copy + B-fragment table (once per CTA) ----
    if (tid < 64) sb2[tid] = __ldg(b2 + tid);
#pragma unroll
    for (int f = tid; f < 2048; f += 128) {
        int w      = f & 3;
        int lane_i = (f >> 2) & 31;
        int g      = (f >> 7) & 7;
        int half   = f >> 10;
        int nt_l   = g >> 1;
        int kt     = g & 1;
        int n  = (half * 4 + nt_l) * 8 + (lane_i >> 2);
        int k0 = kt * 16 + 2 * (lane_i & 3) + (w & 1) * 8;
        float w0 = __ldg(W2 + (k0 + 0) * 64 + n);
        float w1 = __ldg(W2 + (k0 + 1) * 64 + n);
        __nv_bfloat16 h0 = __float2bfloat16(w0);
        __nv_bfloat16 h1 = __float2bfloat16(w1);
        uint32_t val;
        if ((w >> 1) == 0) {
            val = pack_bf16x2(h0, h1);
        } else {
            val = pack_bf16x2(__float2bfloat16(w0 - __bfloat162float(h0)),
                              __float2bfloat16(w1 - __bfloat162float(h1)));
        }
        sBF[half][g][lane_i][w] = val;
    }
    __syncthreads();

    char* wt = sAD[wid];
    uint32_t tile_base = smem_u32(wt);

    int eslot = lane >> 3;
    int echunk = lane & 7;
    float4 w1d4 = __ldg(reinterpret_cast<const float4*>(W1 + 4 * 32) + echunk);

    uint32_t lrow   = ((lane >> 3) & 1) * 8 + (lane & 7);
    uint32_t lchunk = (lane >> 4) * 16;

    int gwarp = blk * 4 + wid;

#pragma unroll 1
    for (int tile = 0; tile < 2; ++tile) {
        int ebase = gwarp * 64 + tile * 32;
        int s    = __ldg(src + ebase + lane);
        int d    = __ldg(dst + ebase + lane);
        float dv = __ldg(dis + ebase + lane);

        // ---- stage hid tile (hi/lo bf16): 8 iterations x 4 edges ----
#pragma unroll 2
        for (int t = 0; t < 8; ++t) {
            int e = t * 4 + eslot;
            int ss   = __shfl_sync(0xffffffffu, s, e);
            int dd   = __shfl_sync(0xffffffffu, d, e);
            float dw = __shfl_sync(0xffffffffu, dv, e);
            float4 av = __ldg(reinterpret_cast<const float4*>(Asrc + ss * 32) + echunk);
            float4 bv = __ldg(reinterpret_cast<const float4*>(Bdst + dd * 32) + echunk);
            float h0 = leaky(av.x + bv.x + dw * w1d4.x);
            float h1 = leaky(av.y + bv.y + dw * w1d4.y);
            float h2 = leaky(av.z + bv.z + dw * w1d4.z);
            float h3 = leaky(av.w + bv.w + dw * w1d4.w);
            uint32_t hi01 = cvt_bf16x2(h0, h1);
            uint32_t hi23 = cvt_bf16x2(h2, h3);
            float l0 = h0 - __uint_as_float(hi01 << 16);
            float l1 = h1 - __uint_as_float(hi01 & 0xffff0000u);
            float l2 = h2 - __uint_as_float(hi23 << 16);
            float l3 = h3 - __uint_as_float(hi23 & 0xffff0000u);
            uint32_t lo01 = cvt_bf16x2(l0, l1);
            uint32_t lo23 = cvt_bf16x2(l2, l3);
            char* rowp = wt + e * AROWB + echunk * 8;
            *reinterpret_cast<uint2*>(rowp)      = make_uint2(hi01, hi23);
            *reinterpret_cast<uint2*>(rowp + 64) = make_uint2(lo01, lo23);
        }
        __syncwarp();

        // ---- all A fragments up front (A-tile free before D overwrites) ----
        uint32_t ah[2][2][4], al[2][2][4];
#pragma unroll
        for (int mt = 0; mt < 2; ++mt) {
            uint32_t rbase = tile_base + (mt * 16 + lrow) * AROWB + lchunk;
            ldsm_x4(rbase + 0,  ah[mt][0][0], ah[mt][0][1], ah[mt][0][2], ah[mt][0][3]);
            ldsm_x4(rbase + 32, ah[mt][1][0], ah[mt][1][1], ah[mt][1][2], ah[mt][1][3]);
            ldsm_x4(rbase + 64, al[mt][0][0], al[mt][0][1], al[mt][0][2], al[mt][0][3]);
            ldsm_x4(rbase + 96, al[mt][1][0], al[mt][1][1], al[mt][1][2], al[mt][1][3]);
        }
        __syncwarp();

        // ---- MMA + store raw D tile (stride DSTR, conflict-free) ----
#pragma unroll
        for (int half = 0; half < 2; ++half) {
            uint32_t Bh[4][2][2], Bl[4][2][2];
#pragma unroll
            for (int g = 0; g < 8; ++g) {
                uint4 v = *reinterpret_cast<const uint4*>(&sBF[half][g][lane][0]);
                int nt = g >> 1, kt = g & 1;
                Bh[nt][kt][0] = v.x;
                Bh[nt][kt][1] = v.y;
                Bl[nt][kt][0] = v.z;
                Bl[nt][kt][1] = v.w;
            }
#pragma unroll
            for (int mt = 0; mt < 2; ++mt) {
                float C[4][4];
#pragma unroll
                for (int nt = 0; nt < 4; ++nt) {
                    float2 bb = *reinterpret_cast<const float2*>(
                        &sb2[(half * 4 + nt) * 8 + 2 * (lane & 3)]);
                    C[nt][0] = bb.x; C[nt][1] = bb.y;
                    C[nt][2] = bb.x; C[nt][3] = bb.y;
                }
#pragma unroll
                for (int nt = 0; nt < 4; ++nt) {
#pragma unroll
                    for (int kt = 0; kt < 2; ++kt) {
                        mma_bf16(C[nt][0], C[nt][1], C[nt][2], C[nt][3],
                                 ah[mt][kt][0], ah[mt][kt][1], ah[mt][kt][2], ah[mt][kt][3],
                                 Bh[nt][kt][0], Bh[nt][kt][1]);
                        mma_bf16(C[nt][0], C[nt][1], C[nt][2], C[nt][3],
                                 ah[mt][kt][0], ah[mt][kt][1], ah[mt][kt][2], ah[mt][kt][3],
                                 Bl[nt][kt][0], Bl[nt][kt][1]);
                        mma_bf16(C[nt][0], C[nt][1], C[nt][2], C[nt][3],
                                 al[mt][kt][0], al[mt][kt][1], al[mt][kt][2], al[mt][kt][3],
                                 Bh[nt][kt][0], Bh[nt][kt][1]);
                    }
                }
                // rows: mt*16 + (lane>>2) and +8; col bytes: half*128 + nt*32 + 8*(lane&3)
                char* drow = wt + (mt * 16 + (lane >> 2)) * DSTR
                           + half * 128 + 8 * (lane & 3);
#pragma unroll
                for (int nt = 0; nt < 4; ++nt) {
                    *reinterpret_cast<float2*>(drow + nt * 32) =
                        make_float2(C[nt][0], C[nt][1]);
                    *reinterpret_cast<float2*>(drow + 8 * DSTR + nt * 32) =
                        make_float2(C[nt][2], C[nt][3]);
                }
            }
        }
        __syncwarp();

        // ---- epilogue: per edge, ONE row-contiguous 32-lane red.v2 ----
#pragma unroll 4
        for (int t = 0; t < 32; ++t) {
            int ddt = __shfl_sync(0xffffffffu, d, t);
            float2 v = *reinterpret_cast<const float2*>(wt + t * DSTR + lane * 8);
            red_v2(sumbuf + (size_t)ddt * 64 + 2 * lane,
                   tanh_fast(v.x), tanh_fast(v.y));
        }
        __syncwarp();
    }
}

// ---------------------------------------------------------------------------
// Node update (unchanged)
// ---------------------------------------------------------------------------
__global__ void __launch_bounds__(256) upd_kernel(
    const float* __restrict__ pos_s,
    const float* __restrict__ h,
    const float* __restrict__ W1,
    const float* __restrict__ b1,
    const float* __restrict__ W2,
    const float* __restrict__ b2,
    float* __restrict__ out)
{
    int lane = threadIdx.x & 31;
    int node = (blockIdx.x * blockDim.x + threadIdx.x) >> 5;
    if (node >= NS) return;
    float p0 = __ldg(pos_s + 2 * node);
    float p1 = __ldg(pos_s + 2 * node + 1);
    float acc = __ldg(b1 + lane)
              + p0 * __ldg(W1 + 0 * 32 + lane)
              + p1 * __ldg(W1 + 1 * 32 + lane);

    const float4* h4  = reinterpret_cast<const float4*>(h) + node * 16;
    const float4* su4 = reinterpret_cast<const float4*>(g_sum_u) + node * 16;
    const float4* sh4 = reinterpret_cast<const float4*>(g_sum_h) + node * 16;
#pragma unroll
    for (int q = 0; q < 16; ++q) {
        float4 v = __ldg(h4 + q);
        acc = fmaf(v.x, __ldg(W1 + (2 + 4 * q + 0) * 32 + lane), acc);
        acc = fmaf(v.y, __ldg(W1 + (2 + 4 * q + 1) * 32 + lane), acc);
        acc = fmaf(v.z, __ldg(W1 + (2 + 4 * q + 2) * 32 + lane), acc);
        acc = fmaf(v.w, __ldg(W1 + (2 + 4 * q + 3) * 32 + lane), acc);
    }
#pragma unroll
    for (int q = 0; q < 16; ++q) {
        float4 v = su4[q];
        acc = fmaf(v.x, __ldg(W1 + (66 + 4 * q + 0) * 32 + lane), acc);
        acc = fmaf(v.y, __ldg(W1 + (66 + 4 * q + 1) * 32 + lane), acc);
        acc = fmaf(v.z, __ldg(W1 + (66 + 4 * q + 2) * 32 + lane), acc);
        acc = fmaf(v.w, __ldg(W1 + (66 + 4 * q + 3) * 32 + lane), acc);
    }
#pragma unroll
    for (int q = 0; q < 16; ++q) {
        float4 v = sh4[q];
        acc = fmaf(v.x, __ldg(W1 + (130 + 4 * q + 0) * 32 + lane), acc);
        acc = fmaf(v.y, __ldg(W1 + (130 + 4 * q + 1) * 32 + lane), acc);
        acc = fmaf(v.z, __ldg(W1 + (130 + 4 * q + 2) * 32 + lane), acc);
        acc = fmaf(v.w, __ldg(W1 + (130 + 4 * q + 3) * 32 + lane), acc);
    }
    acc = leaky(acc);

    float m0 = __ldg(b2 + 2 * lane);
    float m1 = __ldg(b2 + 2 * lane + 1);
#pragma unroll
    for (int k = 0; k < 32; ++k) {
        float hv = __shfl_sync(0xffffffffu, acc, k);
        float2 wv = __ldg(reinterpret_cast<const float2*>(W2 + k * 64) + lane);
        m0 = fmaf(hv, wv.x, m0);
        m1 = fmaf(hv, wv.y, m1);
    }
    float2 o;
    o.x = tanhf(m0);
    o.y = tanhf(m1);
    reinterpret_cast<float2*>(out)[node * 32 + lane] = o;
}

// ---------------------------------------------------------------------------
extern "C" void kernel_launch(void* const* d_in, const int* in_sizes, int n_in,
                              void* d_out, int out_size)
{
    const float* h        = (const float*)d_in[0];
    const float* u        = (const float*)d_in[1];
    const float* pos_s    = (const float*)d_in[2];
    const float* pos_a    = (const float*)d_in[3];
    const float* dis_a2s  = (const float*)d_in[4];
    const float* dis_s2s  = (const float*)d_in[5];
    const int*   a2s_src  = (const int*)d_in[6];
    const int*   a2s_dst  = (const int*)d_in[7];
    const int*   s2s_src  = (const int*)d_in[8];
    const int*   s2s_dst  = (const int*)d_in[9];
    const float* a2s_W1   = (const float*)d_in[10];
    const float* a2s_b1   = (const float*)d_in[11];
    const float* a2s_W2   = (const float*)d_in[12];
    const float* a2s_b2   = (const float*)d_in[13];
    const float* s2s_W1   = (const float*)d_in[14];
    const float* s2s_b1   = (const float*)d_in[15];
    const float* s2s_W2   = (const float*)d_in[16];
    const float* s2s_b2   = (const float*)d_in[17];
    const float* upd_W1   = (const float*)d_in[18];
    const float* upd_b1   = (const float*)d_in[19];
    const float* upd_W2   = (const float*)d_in[20];
    const float* upd_b2   = (const float*)d_in[21];
    float* out = (float*)d_out;

    const int WPB = 8;

    // Launch-order padding: edge_mma_kernel lands at overall launch #4.
    noop_kernel<<<1, 32>>>();
    noop_kernel<<<1, 32>>>();

    // Fused node-side precompute
    int pre_tasks = NS + NA + NS;
    pre_kernel<<<(pre_tasks + WPB - 1) / WPB, 256>>>(
        pos_s, pos_a, u, h, a2s_W1, a2s_b1, s2s_W1, s2s_b1);

    // Edge passes on tensor cores (mma.sync): 256 edges per CTA
    int eb = NEDGE / 256;                 // 6250 per pass
    edge_mma_kernel<<<2 * eb, 128>>>(
        eb,
        a2s_src, a2s_dst, dis_a2s, a2s_W1, a2s_W2, a2s_b2,
        s2s_src, s2s_dst, dis_s2s, s2s_W1, s2s_W2, s2s_b2);

    // Node update
    upd_kernel<<<(NS + WPB - 1) / WPB, 256>>>(pos_s, h, upd_W1, upd_b1, upd_W2, upd_b2, out);
}